// round 16
// baseline (speedup 1.0000x reference)
#include <cuda_runtime.h>
#include <cuda_fp16.h>
#include <cstdint>
#include <cstddef>

// GGNN: B=8, N=1024, H=64, E=2, NUM_STEPS=5
// s = adj @ G, G = [h@C_in0; h@C_in1; h@C_out0; h@C_out1] + d  (C = W_edge x W_gate folded)
// z = sigmoid(s + h@Wg3 + bg); h~ = tanh(s + (z*h)@Wg3 + bg); h = (1-z)h + z*h~
// R16: R14 config + gemm NSTG=3 -> 4 CTAs/SM -> 512 CTAs in ONE wave.

#define NSTEPS 5
#define BB 8
#define NN 1024
#define KSPLIT 4

// ---------------- scratch (device globals; no allocations allowed) ----------------
__device__ __align__(16) __half g_adjh[(size_t)BB * NN * 4096];  // fp16 adj (64MB)
__device__ float g_C[64 * 320];                    // tf32-rounded C (gbuild)
__device__ __half g_Ch[64 * 320];                  // fp16 C (update kernel)
__device__ float g_d[320];                         // folded biases (block 4 = 0)
__device__ __align__(16) __half g_Gh[(size_t)BB * 4096 * 64];    // fp16 B operand
__device__ float g_u[(size_t)BB * 1024 * 64];      // u = h @ Wg3 (fp32)
__device__ float g_h[(size_t)BB * 1024 * 64];      // hidden state
__device__ __align__(16) float g_spart[(size_t)KSPLIT * BB * NN * 64];  // split-K partials (8MB)

// ---------------- helpers ----------------
__device__ __forceinline__ unsigned f2tf(float x) {
    unsigned r;
    asm("cvt.rna.tf32.f32 %0, %1;" : "=r"(r) : "f"(x));
    return r;
}
__device__ __forceinline__ float roundtf(float x) { return __uint_as_float(f2tf(x)); }

__device__ __forceinline__ uint64_t pol_evict_last() {
    uint64_t p;
    asm("createpolicy.fractional.L2::evict_last.b64 %0, 1.0;" : "=l"(p));
    return p;
}

__device__ __forceinline__ void mma8(float c[4], unsigned a0, unsigned a1, unsigned a2, unsigned a3,
                                     unsigned b0, unsigned b1) {
    asm volatile(
        "mma.sync.aligned.m16n8k8.row.col.f32.tf32.tf32.f32 "
        "{%0,%1,%2,%3}, {%4,%5,%6,%7}, {%8,%9}, {%0,%1,%2,%3};"
        : "+f"(c[0]), "+f"(c[1]), "+f"(c[2]), "+f"(c[3])
        : "r"(a0), "r"(a1), "r"(a2), "r"(a3), "r"(b0), "r"(b1));
}

__device__ __forceinline__ void mma16(float c[4], const unsigned a[4], unsigned b0, unsigned b1) {
    asm volatile(
        "mma.sync.aligned.m16n8k16.row.col.f32.f16.f16.f32 "
        "{%0,%1,%2,%3}, {%4,%5,%6,%7}, {%8,%9}, {%0,%1,%2,%3};"
        : "+f"(c[0]), "+f"(c[1]), "+f"(c[2]), "+f"(c[3])
        : "r"(a[0]), "r"(a[1]), "r"(a[2]), "r"(a[3]), "r"(b0), "r"(b1));
}

__device__ __forceinline__ void ldsmx4(unsigned r[4], unsigned sa) {
    asm volatile("ldmatrix.sync.aligned.m8n8.x4.shared.b16 {%0,%1,%2,%3}, [%4];"
                 : "=r"(r[0]), "=r"(r[1]), "=r"(r[2]), "=r"(r[3]) : "r"(sa));
}
__device__ __forceinline__ void ldsmx4t(unsigned r[4], unsigned sa) {
    asm volatile("ldmatrix.sync.aligned.m8n8.x4.trans.shared.b16 {%0,%1,%2,%3}, [%4];"
                 : "=r"(r[0]), "=r"(r[1]), "=r"(r[2]), "=r"(r[3]) : "r"(sa));
}

__device__ __forceinline__ void cpa16(void* smem_dst, const void* gsrc) {
    unsigned s = (unsigned)__cvta_generic_to_shared(smem_dst);
    asm volatile("cp.async.cg.shared.global [%0], [%1], 16;" :: "r"(s), "l"(gsrc) : "memory");
}
__device__ __forceinline__ void cpa16_pol(void* smem_dst, const void* gsrc, uint64_t pol) {
    unsigned s = (unsigned)__cvta_generic_to_shared(smem_dst);
    asm volatile("cp.async.cg.shared.global.L2::cache_hint [%0], [%1], 16, %2;"
                 :: "r"(s), "l"(gsrc), "l"(pol) : "memory");
}
#define CP_COMMIT() asm volatile("cp.async.commit_group;" ::: "memory")

// fp16 warp tile 16x32 over K=64 (update kernel). lda/ldb in halfs.
__device__ __forceinline__ void warptile16(const __half* Ah, int lda, const __half* Bh, int ldb,
                                           float acc[4][4], int mb, int nb, int lane) {
    int rowp = lane & 15;
    int colp = (lane >> 4) << 3;  // 0 or 8 (halfs)
    unsigned sA = (unsigned)__cvta_generic_to_shared(Ah);
    unsigned sB = (unsigned)__cvta_generic_to_shared(Bh);
#pragma unroll
    for (int kk = 0; kk < 4; kk++) {
        int k0 = kk * 16;
        unsigned a[4], b0[4], b1[4];
        ldsmx4(a, sA + (unsigned)(((mb + rowp) * lda) + k0 + colp) * 2u);
        ldsmx4t(b0, sB + (unsigned)(((k0 + rowp) * ldb) + nb + colp) * 2u);
        ldsmx4t(b1, sB + (unsigned)(((k0 + rowp) * ldb) + nb + 16 + colp) * 2u);
        mma16(acc[0], a, b0[0], b0[1]);
        mma16(acc[1], a, b0[2], b0[3]);
        mma16(acc[2], a, b1[0], b1[1]);
        mma16(acc[3], a, b1[2], b1[3]);
    }
}

// fp16 warp tile 32x32 over K=64 (gemm kernel).
__device__ __forceinline__ void warptile32(const __half* Ah, int lda, const __half* Bh, int ldb,
                                           float acc[2][4][4], int mb, int nb, int lane) {
    int rowp = lane & 15;
    int colp = (lane >> 4) << 3;
    unsigned sA = (unsigned)__cvta_generic_to_shared(Ah);
    unsigned sB = (unsigned)__cvta_generic_to_shared(Bh);
#pragma unroll
    for (int kk = 0; kk < 4; kk++) {
        int k0 = kk * 16;
        unsigned a0[4], a1[4], b0[4], b1[4];
        ldsmx4(a0, sA + (unsigned)(((mb + rowp) * lda) + k0 + colp) * 2u);
        ldsmx4(a1, sA + (unsigned)(((mb + 16 + rowp) * lda) + k0 + colp) * 2u);
        ldsmx4t(b0, sB + (unsigned)(((k0 + rowp) * ldb) + nb + colp) * 2u);
        ldsmx4t(b1, sB + (unsigned)(((k0 + rowp) * ldb) + nb + 16 + colp) * 2u);
        mma16(acc[0][0], a0, b0[0], b0[1]);
        mma16(acc[0][1], a0, b0[2], b0[3]);
        mma16(acc[0][2], a0, b1[0], b1[1]);
        mma16(acc[0][3], a0, b1[2], b1[3]);
        mma16(acc[1][0], a1, b0[0], b0[1]);
        mma16(acc[1][1], a1, b0[2], b0[3]);
        mma16(acc[1][2], a1, b1[0], b1[1]);
        mma16(acc[1][3], a1, b1[2], b1[3]);
    }
}

// tf32 warp tile (gbuild only)
__device__ __forceinline__ void warptile64(const float* As, int lda, const float* Bs, int ldb,
                                           float acc[2][4][4], int mb, int nb, int g, int tg) {
#pragma unroll
    for (int kk = 0; kk < 8; kk++) {
        int k0 = kk * 8;
        unsigned a[2][4];
        unsigned b[4][2];
#pragma unroll
        for (int mf = 0; mf < 2; mf++) {
            const float* ap = As + (mb + mf * 16) * lda + k0;
            a[mf][0] = f2tf(ap[g * lda + tg]);
            a[mf][1] = f2tf(ap[(g + 8) * lda + tg]);
            a[mf][2] = f2tf(ap[g * lda + tg + 4]);
            a[mf][3] = f2tf(ap[(g + 8) * lda + tg + 4]);
        }
#pragma unroll
        for (int nf = 0; nf < 4; nf++) {
            const float* bp = Bs + k0 * ldb + nb + nf * 8 + g;
            b[nf][0] = __float_as_uint(bp[tg * ldb]);
            b[nf][1] = __float_as_uint(bp[(tg + 4) * ldb]);
        }
#pragma unroll
        for (int mf = 0; mf < 2; mf++)
#pragma unroll
            for (int nf = 0; nf < 4; nf++)
                mma8(acc[mf][nf], a[mf][0], a[mf][1], a[mf][2], a[mf][3], b[nf][0], b[nf][1]);
    }
}

// ---------------- kernel A: adj fp32 -> fp16 ----------------
__global__ __launch_bounds__(256) void conv_kernel(const float4* __restrict__ a) {
    size_t i = (size_t)blockIdx.x * 256 + threadIdx.x;
    float4 v0 = a[2 * i];
    float4 v1 = a[2 * i + 1];
    __half2 p0 = __floats2half2_rn(v0.x, v0.y);
    __half2 p1 = __floats2half2_rn(v0.z, v0.w);
    __half2 p2 = __floats2half2_rn(v1.x, v1.y);
    __half2 p3 = __floats2half2_rn(v1.z, v1.w);
    uint4 o;
    o.x = *(unsigned*)&p0; o.y = *(unsigned*)&p1;
    o.z = *(unsigned*)&p2; o.w = *(unsigned*)&p3;
    ((uint4*)g_adjh)[i] = o;
}

// ---------------- kernel 0: fold weights into C and d ----------------
__global__ void build_C_kernel(const float* __restrict__ We, const float* __restrict__ be,
                               const float* __restrict__ Wg) {
    int idx = blockIdx.x * 256 + threadIdx.x;
    if (idx < 64 * 320) {
        int hp = idx / 320, c = idx % 320;
        int blk = c / 64, j = c % 64;
        float acc;
        if (blk < 4) {
            acc = 0.f;
            int e = blk & 1;
            int go = (blk < 2) ? 0 : 64;
            for (int h = 0; h < 64; h++) acc += We[hp * 128 + 2 * h + e] * Wg[(go + h) * 64 + j];
        } else {
            acc = Wg[(128 + hp) * 64 + j];  // Wg3
        }
        g_C[hp * 320 + c] = roundtf(acc);
        g_Ch[hp * 320 + c] = __float2half_rn(acc);
    }
    if (idx < 320) {
        int blk = idx / 64, j = idx % 64;
        float acc = 0.f;
        if (blk < 4) {
            int e = blk & 1;
            int go = (blk < 2) ? 0 : 64;
            for (int h = 0; h < 64; h++) acc += be[2 * h + e] * Wg[(go + h) * 64 + j];
        }
        g_d[idx] = acc;
    }
}

// ---------------- kernel 1: G build from initial h (step 0 only) ----------------
#define GB_SMEM (64 * 68 * 4 + 2 * 64 * 72 * 4)

__global__ __launch_bounds__(128) void gbuild_kernel() {
    extern __shared__ __align__(16) char smraw[];
    float* As = (float*)smraw;
    float* Cs = As + 64 * 68;
    int tid = threadIdx.x;
    int mt = blockIdx.x, b = blockIdx.y;
    int m0 = mt * 64;
    const float* hb = g_h + (size_t)b * NN * 64;
#pragma unroll
    for (int i = 0; i < 8; i++) {
        int idx = tid + i * 128;
        int row = idx >> 4, c4 = idx & 15;
        *(float4*)&As[row * 68 + c4 * 4] = *(const float4*)&hb[(size_t)(m0 + row) * 64 + c4 * 4];
        cpa16(Cs + row * 72 + c4 * 4, g_C + row * 320 + c4 * 4);
    }
    CP_COMMIT();

    int warp = tid >> 5, lane = tid & 31, g = lane >> 2, tg = lane & 3;
    int mb = (warp >> 1) * 32, nb = (warp & 1) * 32;

    for (int nt = 0; nt < 5; nt++) {
        float* Ccur = Cs + (nt & 1) * (64 * 72);
        if (nt < 4) {
            float* Cnext = Cs + ((nt + 1) & 1) * (64 * 72);
#pragma unroll
            for (int i = 0; i < 8; i++) {
                int idx = tid + i * 128;
                int row = idx >> 4, c4 = idx & 15;
                cpa16(Cnext + row * 72 + c4 * 4, g_C + row * 320 + (nt + 1) * 64 + c4 * 4);
            }
            CP_COMMIT();
            asm volatile("cp.async.wait_group 1;" ::: "memory");
        } else {
            asm volatile("cp.async.wait_group 0;" ::: "memory");
        }
        __syncthreads();

        float acc[2][4][4] = {};
        warptile64(As, 68, Ccur, 72, acc, mb, nb, g, tg);

#pragma unroll
        for (int mf = 0; mf < 2; mf++)
#pragma unroll
            for (int nf = 0; nf < 4; nf++) {
                int r0 = mb + mf * 16 + g, c0 = nb + nf * 8 + 2 * tg;
#pragma unroll
                for (int q = 0; q < 4; q++) {
                    int lr = r0 + ((q >= 2) ? 8 : 0);
                    int cc = c0 + (q & 1);
                    float val = acc[mf][nf][q] + g_d[nt * 64 + cc];
                    if (nt < 4)
                        g_Gh[((size_t)b * 4096 + nt * 1024 + m0 + lr) * 64 + cc] = __float2half_rn(val);
                    else
                        g_u[((size_t)b * 1024 + m0 + lr) * 64 + cc] = val;
                }
            }
        __syncthreads();
    }
}

// ---------------- kernel 2: split-K GEMM (BM=64, 32x32 warp tiles, single wave) --------
#define STG_A (64 * 72)
#define STG_B (64 * 72)
#define STG_HALFS (STG_A + STG_B)         // 9216 halfs = 18432 B
#define NSTG 3
#define GEMM_SMEM (NSTG * STG_HALFS * 2)  // 55296 B -> 4 CTAs/SM -> 512 CTAs in 1 wave
#define KT_PER_CTA 16                     // 64 k-tiles / KSPLIT

__device__ __forceinline__ void load_stage(__half* stg, const __half* __restrict__ adjb,
                                           const __half* __restrict__ Gb, int m0, int kt, int tid,
                                           uint64_t pol) {
    int k0 = kt * 64;
    __half* As = stg;
    __half* Bs = stg + STG_A;
#pragma unroll
    for (int i = 0; i < 4; i++) {
        int idx = tid + i * 128;
        int row = idx >> 3, c8 = idx & 7;
        cpa16_pol(As + row * 72 + c8 * 8, adjb + (size_t)(m0 + row) * 4096 + k0 + c8 * 8, pol);
    }
#pragma unroll
    for (int i = 0; i < 4; i++) {
        int idx = tid + i * 128;
        int row = idx >> 3, c8 = idx & 7;
        cpa16(Bs + row * 72 + c8 * 8, Gb + (size_t)(k0 + row) * 64 + c8 * 8);
    }
}

__global__ __launch_bounds__(128, 4) void gemm_kernel() {
    extern __shared__ __align__(16) char smraw[];
    __half* smh = (__half*)smraw;
    int tid = threadIdx.x;
    int mt = blockIdx.x, b = blockIdx.y, ks = blockIdx.z;
    int m0 = mt * 64;
    int kb = ks * KT_PER_CTA;
    const __half* adjb = g_adjh + (size_t)b * NN * 4096;
    const __half* Gb = g_Gh + (size_t)b * 4096 * 64;
    uint64_t pol = pol_evict_last();

#pragma unroll
    for (int p = 0; p < NSTG - 1; p++) {
        load_stage(smh + p * STG_HALFS, adjb, Gb, m0, kb + p, tid, pol);
        CP_COMMIT();
    }

    int warp = tid >> 5, lane = tid & 31;
    int mb = (warp >> 1) * 32, nb = (warp & 1) * 32;
    float acc[2][4][4] = {};

    for (int i = 0; i < KT_PER_CTA; i++) {
        asm volatile("cp.async.wait_group %0;" :: "n"(NSTG - 2) : "memory");
        __syncthreads();
        __half* As = smh + (i % NSTG) * STG_HALFS;
        warptile32(As, 72, As + STG_A, 72, acc, mb, nb, lane);
        // stage (i+NSTG-1)%NSTG was consumed at i-1; barrier above covers it.
        if (i + NSTG - 1 < KT_PER_CTA)
            load_stage(smh + ((i + NSTG - 1) % NSTG) * STG_HALFS, adjb, Gb, m0,
                       kb + i + NSTG - 1, tid, pol);
        CP_COMMIT();
    }

    float* sp = g_spart + ((size_t)ks * BB + b) * NN * 64;
    int g = lane >> 2, tg = lane & 3;
#pragma unroll
    for (int mf = 0; mf < 2; mf++)
#pragma unroll
        for (int nf = 0; nf < 4; nf++) {
            int r0 = mb + mf * 16 + g, c0 = nb + nf * 8 + 2 * tg;
            float2 p0 = {acc[mf][nf][0], acc[mf][nf][1]};
            float2 p1 = {acc[mf][nf][2], acc[mf][nf][3]};
            *(float2*)&sp[(size_t)(m0 + r0) * 64 + c0] = p0;
            *(float2*)&sp[(size_t)(m0 + r0 + 8) * 64 + c0] = p1;
        }
}

// ---------------- kernel 3: update — BM=64/256t, gate + h update + next G build -------
// smem: Spre(64x68 f32) | Zs(64x68 f32) | Wsh(64x72 h) | hnewh(64x72 h) | Ch(64x328 h)
#define UPD_SMEM (64 * 68 * 4 * 2 + 64 * 72 * 2 * 2 + 64 * 328 * 2)  // 95232 B

__global__ __launch_bounds__(256) void update_kernel(const float* __restrict__ bgate,
                                                     int build_g) {
    extern __shared__ __align__(16) char sm[];
    float* Spre = (float*)sm;
    float* Zs = Spre + 64 * 68;
    __half* Wsh = (__half*)(Zs + 64 * 68);
    __half* hnewh = Wsh + 64 * 72;
    __half* Ch = hnewh + 64 * 72;

    int tid = threadIdx.x;
    int mt = blockIdx.x, b = blockIdx.y;
    int m0 = mt * 64;
    int warp = tid >> 5, lane = tid & 31, g = lane >> 2, tg = lane & 3;

    // async-load full fp16 C (stride 328)
    for (int i = tid; i < 2560; i += 256) {
        int row = i / 40, c = i % 40;
        cpa16(Ch + row * 328 + c * 8, g_Ch + row * 320 + c * 8);
    }
    CP_COMMIT();

    // ---- stage 1: gate (thread -> row tid>>2, 16 cols) ----
    {
        int r = tid >> 2, cb = (tid & 3) * 16;
        const float* s0 = g_spart + ((size_t)b * NN + m0 + r) * 64;
        const float* s1 = s0 + (size_t)BB * NN * 64;
        const float* s2 = s1 + (size_t)BB * NN * 64;
        const float* s3 = s2 + (size_t)BB * NN * 64;
        const float* urow = g_u + ((size_t)b * NN + m0 + r) * 64;
        const float* hrow = g_h + ((size_t)b * NN + m0 + r) * 64;
#pragma unroll
        for (int v = 0; v < 4; v++) {
            int c = cb + v * 4;
            float4 q0 = *(const float4*)&s0[c];
            float4 q1 = *(const float4*)&s1[c];
            float4 q2 = *(const float4*)&s2[c];
            float4 q3 = *(const float4*)&s3[c];
            float4 uq = *(const float4*)&urow[c];
            float4 hq = *(const float4*)&hrow[c];
            float sp0 = (q0.x + q1.x) + (q2.x + q3.x) + bgate[c + 0];
            float sp1 = (q0.y + q1.y) + (q2.y + q3.y) + bgate[c + 1];
            float sp2 = (q0.z + q1.z) + (q2.z + q3.z) + bgate[c + 2];
            float sp3 = (q0.w + q1.w) + (q2.w + q3.w) + bgate[c + 3];
            float z0 = 1.f / (1.f + __expf(-(sp0 + uq.x)));
            float z1 = 1.f / (1.f + __expf(-(sp1 + uq.y)));
            float z2 = 1.f / (1.f + __expf(-(sp2 + uq.z)));
            float z3 = 1.f / (1.f + __expf(-(sp3 + uq.w)));
            Spre[r * 68 + c + 0] = sp0; Spre[r * 68 + c + 1] = sp1;
            Spre[r * 68 + c + 2] = sp2; Spre[r * 68 + c + 3] = sp3;
            Zs[r * 68 + c + 0] = z0; Zs[r * 68 + c + 1] = z1;
            Zs[r * 68 + c + 2] = z2; Zs[r * 68 + c + 3] = z3;
            __half2 w01 = __floats2half2_rn(z0 * hq.x, z1 * hq.y);
            __half2 w23 = __floats2half2_rn(z2 * hq.z, z3 * hq.w);
            *(__half2*)&Wsh[r * 72 + c + 0] = w01;
            *(__half2*)&Wsh[r * 72 + c + 2] = w23;
        }
    }
    asm volatile("cp.async.wait_group 0;" ::: "memory");
    __syncthreads();

    // ---- stage 2: v = (z*h) @ Wg3 (8 warps, 16x32 tiles), h update ----
    int mb = (warp >> 1) * 16, nb = (warp & 1) * 32;
    float vacc[4][4] = {};
    warptile16(Wsh, 72, Ch + 256, 328, vacc, mb, nb, lane);  // Wg3 = C cols 256..319

    float* hb = g_h + (size_t)b * NN * 64;
#pragma unroll
    for (int nf = 0; nf < 4; nf++) {
        int r0 = mb + g, c0 = nb + nf * 8 + 2 * tg;
#pragma unroll
        for (int q = 0; q < 4; q++) {
            int lr = r0 + ((q >= 2) ? 8 : 0);
            int cc = c0 + (q & 1);
            float z = Zs[lr * 68 + cc];
            float hh = hb[(size_t)(m0 + lr) * 64 + cc];
            float ht = tanhf(Spre[lr * 68 + cc] + vacc[nf][q]);
            float hn = (1.f - z) * hh + z * ht;
            hb[(size_t)(m0 + lr) * 64 + cc] = hn;
            hnewh[lr * 72 + cc] = __float2half_rn(hn);
        }
    }
    __syncthreads();

    // ---- stage 3: next-step G build: G = h_new @ C (+d); chunk 4 -> u ----
    if (build_g) {
        int mbb = (warp >> 1) * 16, nbb = (warp & 1) * 32;
#pragma unroll
        for (int chunk = 0; chunk < 5; chunk++) {
            float ga[4][4] = {};
            warptile16(hnewh, 72, Ch + chunk * 64, 328, ga, mbb, nbb, lane);
#pragma unroll
            for (int nf = 0; nf < 4; nf++) {
                int r0 = mbb + g, c0 = nbb + nf * 8 + 2 * tg;
#pragma unroll
                for (int q = 0; q < 4; q++) {
                    int lr = r0 + ((q >= 2) ? 8 : 0);
                    int cc = c0 + (q & 1);
                    float val = ga[nf][q] + g_d[chunk * 64 + cc];
                    if (chunk < 4)
                        g_Gh[((size_t)b * 4096 + chunk * 1024 + m0 + lr) * 64 + cc] =
                            __float2half_rn(val);
                    else
                        g_u[((size_t)b * NN + m0 + lr) * 64 + cc] = val;
                }
            }
        }
    }
}

// ---------------- kernel 4: final readout ----------------
__global__ __launch_bounds__(256) void final_kernel(const float* __restrict__ ann,
                                                    const float* __restrict__ Wh,
                                                    const float* __restrict__ bh,
                                                    const float* __restrict__ Wo,
                                                    const float* __restrict__ bo,
                                                    float* __restrict__ out) {
    __shared__ float Whs[72 * 64];
    __shared__ float rowbuf[4][72];
    __shared__ float red[4][2];
    int tid = threadIdx.x;
    for (int i = tid; i < 72 * 64; i += 256) Whs[i] = Wh[i];
    int sub = tid >> 6, j = tid & 63;
    int rglob = blockIdx.x * 4 + sub;
    rowbuf[sub][j] = g_h[(size_t)rglob * 64 + j];
    if (j < 8) rowbuf[sub][64 + j] = ann[(size_t)rglob * 8 + j];
    __syncthreads();

    float acc = bh[j];
#pragma unroll
    for (int k = 0; k < 72; k++) acc += rowbuf[sub][k] * Whs[k * 64 + j];
    float o = tanhf(acc) * Wo[j];
#pragma unroll
    for (int off = 16; off; off >>= 1) o += __shfl_down_sync(0xffffffffu, o, off);
    if ((tid & 31) == 0) red[sub][j >> 5] = o;
    __syncthreads();
    if (j == 0) out[rglob] = red[sub][0] + red[sub][1] + bo[0];
}

// ---------------- host ----------------
extern "C" void kernel_launch(void* const* d_in, const int* in_sizes, int n_in,
                              void* d_out, int out_size) {
    (void)in_sizes; (void)n_in; (void)out_size;
    const float* init = (const float*)d_in[0];
    const float* ann  = (const float*)d_in[1];
    const float* adj  = (const float*)d_in[2];
    const float* We   = (const float*)d_in[3];
    const float* be   = (const float*)d_in[4];
    const float* Wg   = (const float*)d_in[5];
    const float* bg   = (const float*)d_in[6];
    const float* Wh   = (const float*)d_in[7];
    const float* bh   = (const float*)d_in[8];
    const float* Wo   = (const float*)d_in[9];
    const float* bo   = (const float*)d_in[10];
    float* out = (float*)d_out;

    cudaFuncSetAttribute(gemm_kernel, cudaFuncAttributeMaxDynamicSharedMemorySize, GEMM_SMEM);
    cudaFuncSetAttribute(update_kernel, cudaFuncAttributeMaxDynamicSharedMemorySize, UPD_SMEM);
    cudaFuncSetAttribute(gbuild_kernel, cudaFuncAttributeMaxDynamicSharedMemorySize, GB_SMEM);

    cudaMemcpyToSymbolAsync(g_h, init, (size_t)BB * NN * 64 * sizeof(float), 0,
                            cudaMemcpyDeviceToDevice, 0);
    conv_kernel<<<16384, 256>>>((const float4*)adj);
    build_C_kernel<<<80, 256>>>(We, be, Wg);
    gbuild_kernel<<<dim3(16, BB), 128, GB_SMEM>>>();
    for (int s = 0; s < NSTEPS; s++) {
        gemm_kernel<<<dim3(16, BB, KSPLIT), 128, GEMM_SMEM>>>();
        update_kernel<<<dim3(16, BB), 256, UPD_SMEM>>>(bg, (s < NSTEPS - 1) ? 1 : 0);
    }
    final_kernel<<<2048, 256>>>(ann, Wh, bh, Wo, bo, out);
}

// round 17
// speedup vs baseline: 1.3696x; 1.3696x over previous
#include <cuda_runtime.h>
#include <cuda_fp16.h>
#include <cstdint>
#include <cstddef>

// GGNN: B=8, N=1024, H=64, E=2, NUM_STEPS=5
// s = adj @ G, G = [h@C_in0; h@C_in1; h@C_out0; h@C_out1] + d  (C = W_edge x W_gate folded)
// z = sigmoid(s + h@Wg3 + bg); h~ = tanh(s + (z*h)@Wg3 + bg); h = (1-z)h + z*h~
// R17: R14 config (NSTG=4, KSPLIT=4, BM=64 gemm; BM=64/256t update) +
// evict_last on adj loads in gemm (R15-measured) + evict_first on conv fp32 reads.

#define NSTEPS 5
#define BB 8
#define NN 1024
#define KSPLIT 4

// ---------------- scratch (device globals; no allocations allowed) ----------------
__device__ __align__(16) __half g_adjh[(size_t)BB * NN * 4096];  // fp16 adj (64MB)
__device__ float g_C[64 * 320];                    // tf32-rounded C (gbuild)
__device__ __half g_Ch[64 * 320];                  // fp16 C (update kernel)
__device__ float g_d[320];                         // folded biases (block 4 = 0)
__device__ __align__(16) __half g_Gh[(size_t)BB * 4096 * 64];    // fp16 B operand
__device__ float g_u[(size_t)BB * 1024 * 64];      // u = h @ Wg3 (fp32)
__device__ float g_h[(size_t)BB * 1024 * 64];      // hidden state
__device__ __align__(16) float g_spart[(size_t)KSPLIT * BB * NN * 64];  // split-K partials (8MB)

// ---------------- helpers ----------------
__device__ __forceinline__ unsigned f2tf(float x) {
    unsigned r;
    asm("cvt.rna.tf32.f32 %0, %1;" : "=r"(r) : "f"(x));
    return r;
}
__device__ __forceinline__ float roundtf(float x) { return __uint_as_float(f2tf(x)); }

__device__ __forceinline__ uint64_t pol_evict_last() {
    uint64_t p;
    asm("createpolicy.fractional.L2::evict_last.b64 %0, 1.0;" : "=l"(p));
    return p;
}
__device__ __forceinline__ uint64_t pol_evict_first() {
    uint64_t p;
    asm("createpolicy.fractional.L2::evict_first.b64 %0, 1.0;" : "=l"(p));
    return p;
}

__device__ __forceinline__ void mma8(float c[4], unsigned a0, unsigned a1, unsigned a2, unsigned a3,
                                     unsigned b0, unsigned b1) {
    asm volatile(
        "mma.sync.aligned.m16n8k8.row.col.f32.tf32.tf32.f32 "
        "{%0,%1,%2,%3}, {%4,%5,%6,%7}, {%8,%9}, {%0,%1,%2,%3};"
        : "+f"(c[0]), "+f"(c[1]), "+f"(c[2]), "+f"(c[3])
        : "r"(a0), "r"(a1), "r"(a2), "r"(a3), "r"(b0), "r"(b1));
}

__device__ __forceinline__ void mma16(float c[4], const unsigned a[4], unsigned b0, unsigned b1) {
    asm volatile(
        "mma.sync.aligned.m16n8k16.row.col.f32.f16.f16.f32 "
        "{%0,%1,%2,%3}, {%4,%5,%6,%7}, {%8,%9}, {%0,%1,%2,%3};"
        : "+f"(c[0]), "+f"(c[1]), "+f"(c[2]), "+f"(c[3])
        : "r"(a[0]), "r"(a[1]), "r"(a[2]), "r"(a[3]), "r"(b0), "r"(b1));
}

__device__ __forceinline__ void ldsmx4(unsigned r[4], unsigned sa) {
    asm volatile("ldmatrix.sync.aligned.m8n8.x4.shared.b16 {%0,%1,%2,%3}, [%4];"
                 : "=r"(r[0]), "=r"(r[1]), "=r"(r[2]), "=r"(r[3]) : "r"(sa));
}
__device__ __forceinline__ void ldsmx4t(unsigned r[4], unsigned sa) {
    asm volatile("ldmatrix.sync.aligned.m8n8.x4.trans.shared.b16 {%0,%1,%2,%3}, [%4];"
                 : "=r"(r[0]), "=r"(r[1]), "=r"(r[2]), "=r"(r[3]) : "r"(sa));
}

__device__ __forceinline__ void cpa16(void* smem_dst, const void* gsrc) {
    unsigned s = (unsigned)__cvta_generic_to_shared(smem_dst);
    asm volatile("cp.async.cg.shared.global [%0], [%1], 16;" :: "r"(s), "l"(gsrc) : "memory");
}
__device__ __forceinline__ void cpa16_pol(void* smem_dst, const void* gsrc, uint64_t pol) {
    unsigned s = (unsigned)__cvta_generic_to_shared(smem_dst);
    asm volatile("cp.async.cg.shared.global.L2::cache_hint [%0], [%1], 16, %2;"
                 :: "r"(s), "l"(gsrc), "l"(pol) : "memory");
}
#define CP_COMMIT() asm volatile("cp.async.commit_group;" ::: "memory")

// fp16 warp tile 16x32 over K=64 (update kernel). lda/ldb in halfs.
__device__ __forceinline__ void warptile16(const __half* Ah, int lda, const __half* Bh, int ldb,
                                           float acc[4][4], int mb, int nb, int lane) {
    int rowp = lane & 15;
    int colp = (lane >> 4) << 3;  // 0 or 8 (halfs)
    unsigned sA = (unsigned)__cvta_generic_to_shared(Ah);
    unsigned sB = (unsigned)__cvta_generic_to_shared(Bh);
#pragma unroll
    for (int kk = 0; kk < 4; kk++) {
        int k0 = kk * 16;
        unsigned a[4], b0[4], b1[4];
        ldsmx4(a, sA + (unsigned)(((mb + rowp) * lda) + k0 + colp) * 2u);
        ldsmx4t(b0, sB + (unsigned)(((k0 + rowp) * ldb) + nb + colp) * 2u);
        ldsmx4t(b1, sB + (unsigned)(((k0 + rowp) * ldb) + nb + 16 + colp) * 2u);
        mma16(acc[0], a, b0[0], b0[1]);
        mma16(acc[1], a, b0[2], b0[3]);
        mma16(acc[2], a, b1[0], b1[1]);
        mma16(acc[3], a, b1[2], b1[3]);
    }
}

// fp16 warp tile 32x32 over K=64 (gemm kernel).
__device__ __forceinline__ void warptile32(const __half* Ah, int lda, const __half* Bh, int ldb,
                                           float acc[2][4][4], int mb, int nb, int lane) {
    int rowp = lane & 15;
    int colp = (lane >> 4) << 3;
    unsigned sA = (unsigned)__cvta_generic_to_shared(Ah);
    unsigned sB = (unsigned)__cvta_generic_to_shared(Bh);
#pragma unroll
    for (int kk = 0; kk < 4; kk++) {
        int k0 = kk * 16;
        unsigned a0[4], a1[4], b0[4], b1[4];
        ldsmx4(a0, sA + (unsigned)(((mb + rowp) * lda) + k0 + colp) * 2u);
        ldsmx4(a1, sA + (unsigned)(((mb + 16 + rowp) * lda) + k0 + colp) * 2u);
        ldsmx4t(b0, sB + (unsigned)(((k0 + rowp) * ldb) + nb + colp) * 2u);
        ldsmx4t(b1, sB + (unsigned)(((k0 + rowp) * ldb) + nb + 16 + colp) * 2u);
        mma16(acc[0][0], a0, b0[0], b0[1]);
        mma16(acc[0][1], a0, b0[2], b0[3]);
        mma16(acc[0][2], a0, b1[0], b1[1]);
        mma16(acc[0][3], a0, b1[2], b1[3]);
        mma16(acc[1][0], a1, b0[0], b0[1]);
        mma16(acc[1][1], a1, b0[2], b0[3]);
        mma16(acc[1][2], a1, b1[0], b1[1]);
        mma16(acc[1][3], a1, b1[2], b1[3]);
    }
}

// tf32 warp tile (gbuild only)
__device__ __forceinline__ void warptile64(const float* As, int lda, const float* Bs, int ldb,
                                           float acc[2][4][4], int mb, int nb, int g, int tg) {
#pragma unroll
    for (int kk = 0; kk < 8; kk++) {
        int k0 = kk * 8;
        unsigned a[2][4];
        unsigned b[4][2];
#pragma unroll
        for (int mf = 0; mf < 2; mf++) {
            const float* ap = As + (mb + mf * 16) * lda + k0;
            a[mf][0] = f2tf(ap[g * lda + tg]);
            a[mf][1] = f2tf(ap[(g + 8) * lda + tg]);
            a[mf][2] = f2tf(ap[g * lda + tg + 4]);
            a[mf][3] = f2tf(ap[(g + 8) * lda + tg + 4]);
        }
#pragma unroll
        for (int nf = 0; nf < 4; nf++) {
            const float* bp = Bs + k0 * ldb + nb + nf * 8 + g;
            b[nf][0] = __float_as_uint(bp[tg * ldb]);
            b[nf][1] = __float_as_uint(bp[(tg + 4) * ldb]);
        }
#pragma unroll
        for (int mf = 0; mf < 2; mf++)
#pragma unroll
            for (int nf = 0; nf < 4; nf++)
                mma8(acc[mf][nf], a[mf][0], a[mf][1], a[mf][2], a[mf][3], b[nf][0], b[nf][1]);
    }
}

// ---------------- kernel A: adj fp32 -> fp16 (fp32 reads marked evict_first) ----------
__global__ __launch_bounds__(256) void conv_kernel(const float4* __restrict__ a) {
    size_t i = (size_t)blockIdx.x * 256 + threadIdx.x;
    uint64_t pf = pol_evict_first();
    float4 v0, v1;
    asm("ld.global.L2::cache_hint.v4.f32 {%0,%1,%2,%3}, [%4], %5;"
        : "=f"(v0.x), "=f"(v0.y), "=f"(v0.z), "=f"(v0.w)
        : "l"(a + 2 * i), "l"(pf));
    asm("ld.global.L2::cache_hint.v4.f32 {%0,%1,%2,%3}, [%4], %5;"
        : "=f"(v1.x), "=f"(v1.y), "=f"(v1.z), "=f"(v1.w)
        : "l"(a + 2 * i + 1), "l"(pf));
    __half2 p0 = __floats2half2_rn(v0.x, v0.y);
    __half2 p1 = __floats2half2_rn(v0.z, v0.w);
    __half2 p2 = __floats2half2_rn(v1.x, v1.y);
    __half2 p3 = __floats2half2_rn(v1.z, v1.w);
    uint4 o;
    o.x = *(unsigned*)&p0; o.y = *(unsigned*)&p1;
    o.z = *(unsigned*)&p2; o.w = *(unsigned*)&p3;
    ((uint4*)g_adjh)[i] = o;
}

// ---------------- kernel 0: fold weights into C and d ----------------
__global__ void build_C_kernel(const float* __restrict__ We, const float* __restrict__ be,
                               const float* __restrict__ Wg) {
    int idx = blockIdx.x * 256 + threadIdx.x;
    if (idx < 64 * 320) {
        int hp = idx / 320, c = idx % 320;
        int blk = c / 64, j = c % 64;
        float acc;
        if (blk < 4) {
            acc = 0.f;
            int e = blk & 1;
            int go = (blk < 2) ? 0 : 64;
            for (int h = 0; h < 64; h++) acc += We[hp * 128 + 2 * h + e] * Wg[(go + h) * 64 + j];
        } else {
            acc = Wg[(128 + hp) * 64 + j];  // Wg3
        }
        g_C[hp * 320 + c] = roundtf(acc);
        g_Ch[hp * 320 + c] = __float2half_rn(acc);
    }
    if (idx < 320) {
        int blk = idx / 64, j = idx % 64;
        float acc = 0.f;
        if (blk < 4) {
            int e = blk & 1;
            int go = (blk < 2) ? 0 : 64;
            for (int h = 0; h < 64; h++) acc += be[2 * h + e] * Wg[(go + h) * 64 + j];
        }
        g_d[idx] = acc;
    }
}

// ---------------- kernel 1: G build from initial h (step 0 only) ----------------
#define GB_SMEM (64 * 68 * 4 + 2 * 64 * 72 * 4)

__global__ __launch_bounds__(128) void gbuild_kernel() {
    extern __shared__ __align__(16) char smraw[];
    float* As = (float*)smraw;
    float* Cs = As + 64 * 68;
    int tid = threadIdx.x;
    int mt = blockIdx.x, b = blockIdx.y;
    int m0 = mt * 64;
    const float* hb = g_h + (size_t)b * NN * 64;
#pragma unroll
    for (int i = 0; i < 8; i++) {
        int idx = tid + i * 128;
        int row = idx >> 4, c4 = idx & 15;
        *(float4*)&As[row * 68 + c4 * 4] = *(const float4*)&hb[(size_t)(m0 + row) * 64 + c4 * 4];
        cpa16(Cs + row * 72 + c4 * 4, g_C + row * 320 + c4 * 4);
    }
    CP_COMMIT();

    int warp = tid >> 5, lane = tid & 31, g = lane >> 2, tg = lane & 3;
    int mb = (warp >> 1) * 32, nb = (warp & 1) * 32;

    for (int nt = 0; nt < 5; nt++) {
        float* Ccur = Cs + (nt & 1) * (64 * 72);
        if (nt < 4) {
            float* Cnext = Cs + ((nt + 1) & 1) * (64 * 72);
#pragma unroll
            for (int i = 0; i < 8; i++) {
                int idx = tid + i * 128;
                int row = idx >> 4, c4 = idx & 15;
                cpa16(Cnext + row * 72 + c4 * 4, g_C + row * 320 + (nt + 1) * 64 + c4 * 4);
            }
            CP_COMMIT();
            asm volatile("cp.async.wait_group 1;" ::: "memory");
        } else {
            asm volatile("cp.async.wait_group 0;" ::: "memory");
        }
        __syncthreads();

        float acc[2][4][4] = {};
        warptile64(As, 68, Ccur, 72, acc, mb, nb, g, tg);

#pragma unroll
        for (int mf = 0; mf < 2; mf++)
#pragma unroll
            for (int nf = 0; nf < 4; nf++) {
                int r0 = mb + mf * 16 + g, c0 = nb + nf * 8 + 2 * tg;
#pragma unroll
                for (int q = 0; q < 4; q++) {
                    int lr = r0 + ((q >= 2) ? 8 : 0);
                    int cc = c0 + (q & 1);
                    float val = acc[mf][nf][q] + g_d[nt * 64 + cc];
                    if (nt < 4)
                        g_Gh[((size_t)b * 4096 + nt * 1024 + m0 + lr) * 64 + cc] = __float2half_rn(val);
                    else
                        g_u[((size_t)b * 1024 + m0 + lr) * 64 + cc] = val;
                }
            }
        __syncthreads();
    }
}

// ---------------- kernel 2: split-K GEMM (BM=64, 32x32 warp tiles, NSTG=4) ------------
#define STG_A (64 * 72)
#define STG_B (64 * 72)
#define STG_HALFS (STG_A + STG_B)         // 9216 halfs = 18432 B
#define NSTG 4
#define GEMM_SMEM (NSTG * STG_HALFS * 2)  // 73728 B -> 3 CTAs/SM
#define KT_PER_CTA 16                     // 64 k-tiles / KSPLIT

__device__ __forceinline__ void load_stage(__half* stg, const __half* __restrict__ adjb,
                                           const __half* __restrict__ Gb, int m0, int kt, int tid,
                                           uint64_t pol) {
    int k0 = kt * 64;
    __half* As = stg;
    __half* Bs = stg + STG_A;
#pragma unroll
    for (int i = 0; i < 4; i++) {
        int idx = tid + i * 128;
        int row = idx >> 3, c8 = idx & 7;
        cpa16_pol(As + row * 72 + c8 * 8, adjb + (size_t)(m0 + row) * 4096 + k0 + c8 * 8, pol);
    }
#pragma unroll
    for (int i = 0; i < 4; i++) {
        int idx = tid + i * 128;
        int row = idx >> 3, c8 = idx & 7;
        cpa16(Bs + row * 72 + c8 * 8, Gb + (size_t)(k0 + row) * 64 + c8 * 8);
    }
}

__global__ __launch_bounds__(128, 3) void gemm_kernel() {
    extern __shared__ __align__(16) char smraw[];
    __half* smh = (__half*)smraw;
    int tid = threadIdx.x;
    int mt = blockIdx.x, b = blockIdx.y, ks = blockIdx.z;
    int m0 = mt * 64;
    int kb = ks * KT_PER_CTA;
    const __half* adjb = g_adjh + (size_t)b * NN * 4096;
    const __half* Gb = g_Gh + (size_t)b * 4096 * 64;
    uint64_t pol = pol_evict_last();

#pragma unroll
    for (int p = 0; p < NSTG - 1; p++) {
        load_stage(smh + p * STG_HALFS, adjb, Gb, m0, kb + p, tid, pol);
        CP_COMMIT();
    }

    int warp = tid >> 5, lane = tid & 31;
    int mb = (warp >> 1) * 32, nb = (warp & 1) * 32;
    float acc[2][4][4] = {};

    for (int i = 0; i < KT_PER_CTA; i++) {
        asm volatile("cp.async.wait_group %0;" :: "n"(NSTG - 2) : "memory");
        __syncthreads();
        __half* As = smh + (i % NSTG) * STG_HALFS;
        warptile32(As, 72, As + STG_A, 72, acc, mb, nb, lane);
        // stage (i+NSTG-1)%NSTG was consumed at i-1; barrier above covers it.
        if (i + NSTG - 1 < KT_PER_CTA)
            load_stage(smh + ((i + NSTG - 1) % NSTG) * STG_HALFS, adjb, Gb, m0,
                       kb + i + NSTG - 1, tid, pol);
        CP_COMMIT();
    }

    float* sp = g_spart + ((size_t)ks * BB + b) * NN * 64;
    int g = lane >> 2, tg = lane & 3;
#pragma unroll
    for (int mf = 0; mf < 2; mf++)
#pragma unroll
        for (int nf = 0; nf < 4; nf++) {
            int r0 = mb + mf * 16 + g, c0 = nb + nf * 8 + 2 * tg;
            float2 p0 = {acc[mf][nf][0], acc[mf][nf][1]};
            float2 p1 = {acc[mf][nf][2], acc[mf][nf][3]};
            *(float2*)&sp[(size_t)(m0 + r0) * 64 + c0] = p0;
            *(float2*)&sp[(size_t)(m0 + r0 + 8) * 64 + c0] = p1;
        }
}

// ---------------- kernel 3: update — BM=64/256t, gate + h update + next G build -------
// smem: Spre(64x68 f32) | Zs(64x68 f32) | Wsh(64x72 h) | hnewh(64x72 h) | Ch(64x328 h)
#define UPD_SMEM (64 * 68 * 4 * 2 + 64 * 72 * 2 * 2 + 64 * 328 * 2)  // 95232 B

__global__ __launch_bounds__(256) void update_kernel(const float* __restrict__ bgate,
                                                     int build_g) {
    extern __shared__ __align__(16) char sm[];
    float* Spre = (float*)sm;
    float* Zs = Spre + 64 * 68;
    __half* Wsh = (__half*)(Zs + 64 * 68);
    __half* hnewh = Wsh + 64 * 72;
    __half* Ch = hnewh + 64 * 72;

    int tid = threadIdx.x;
    int mt = blockIdx.x, b = blockIdx.y;
    int m0 = mt * 64;
    int warp = tid >> 5, lane = tid & 31, g = lane >> 2, tg = lane & 3;

    // async-load full fp16 C (stride 328)
    for (int i = tid; i < 2560; i += 256) {
        int row = i / 40, c = i % 40;
        cpa16(Ch + row * 328 + c * 8, g_Ch + row * 320 + c * 8);
    }
    CP_COMMIT();

    // ---- stage 1: gate (thread -> row tid>>2, 16 cols) ----
    {
        int r = tid >> 2, cb = (tid & 3) * 16;
        const float* s0 = g_spart + ((size_t)b * NN + m0 + r) * 64;
        const float* s1 = s0 + (size_t)BB * NN * 64;
        const float* s2 = s1 + (size_t)BB * NN * 64;
        const float* s3 = s2 + (size_t)BB * NN * 64;
        const float* urow = g_u + ((size_t)b * NN + m0 + r) * 64;
        const float* hrow = g_h + ((size_t)b * NN + m0 + r) * 64;
#pragma unroll
        for (int v = 0; v < 4; v++) {
            int c = cb + v * 4;
            float4 q0 = *(const float4*)&s0[c];
            float4 q1 = *(const float4*)&s1[c];
            float4 q2 = *(const float4*)&s2[c];
            float4 q3 = *(const float4*)&s3[c];
            float4 uq = *(const float4*)&urow[c];
            float4 hq = *(const float4*)&hrow[c];
            float sp0 = (q0.x + q1.x) + (q2.x + q3.x) + bgate[c + 0];
            float sp1 = (q0.y + q1.y) + (q2.y + q3.y) + bgate[c + 1];
            float sp2 = (q0.z + q1.z) + (q2.z + q3.z) + bgate[c + 2];
            float sp3 = (q0.w + q1.w) + (q2.w + q3.w) + bgate[c + 3];
            float z0 = 1.f / (1.f + __expf(-(sp0 + uq.x)));
            float z1 = 1.f / (1.f + __expf(-(sp1 + uq.y)));
            float z2 = 1.f / (1.f + __expf(-(sp2 + uq.z)));
            float z3 = 1.f / (1.f + __expf(-(sp3 + uq.w)));
            Spre[r * 68 + c + 0] = sp0; Spre[r * 68 + c + 1] = sp1;
            Spre[r * 68 + c + 2] = sp2; Spre[r * 68 + c + 3] = sp3;
            Zs[r * 68 + c + 0] = z0; Zs[r * 68 + c + 1] = z1;
            Zs[r * 68 + c + 2] = z2; Zs[r * 68 + c + 3] = z3;
            __half2 w01 = __floats2half2_rn(z0 * hq.x, z1 * hq.y);
            __half2 w23 = __floats2half2_rn(z2 * hq.z, z3 * hq.w);
            *(__half2*)&Wsh[r * 72 + c + 0] = w01;
            *(__half2*)&Wsh[r * 72 + c + 2] = w23;
        }
    }
    asm volatile("cp.async.wait_group 0;" ::: "memory");
    __syncthreads();

    // ---- stage 2: v = (z*h) @ Wg3 (8 warps, 16x32 tiles), h update ----
    int mb = (warp >> 1) * 16, nb = (warp & 1) * 32;
    float vacc[4][4] = {};
    warptile16(Wsh, 72, Ch + 256, 328, vacc, mb, nb, lane);  // Wg3 = C cols 256..319

    float* hb = g_h + (size_t)b * NN * 64;
#pragma unroll
    for (int nf = 0; nf < 4; nf++) {
        int r0 = mb + g, c0 = nb + nf * 8 + 2 * tg;
#pragma unroll
        for (int q = 0; q < 4; q++) {
            int lr = r0 + ((q >= 2) ? 8 : 0);
            int cc = c0 + (q & 1);
            float z = Zs[lr * 68 + cc];
            float hh = hb[(size_t)(m0 + lr) * 64 + cc];
            float ht = tanhf(Spre[lr * 68 + cc] + vacc[nf][q]);
            float hn = (1.f - z) * hh + z * ht;
            hb[(size_t)(m0 + lr) * 64 + cc] = hn;
            hnewh[lr * 72 + cc] = __float2half_rn(hn);
        }
    }
    __syncthreads();

    // ---- stage 3: next-step G build: G = h_new @ C (+d); chunk 4 -> u ----
    if (build_g) {
        int mbb = (warp >> 1) * 16, nbb = (warp & 1) * 32;
#pragma unroll
        for (int chunk = 0; chunk < 5; chunk++) {
            float ga[4][4] = {};
            warptile16(hnewh, 72, Ch + chunk * 64, 328, ga, mbb, nbb, lane);
#pragma unroll
            for (int nf = 0; nf < 4; nf++) {
                int r0 = mbb + g, c0 = nbb + nf * 8 + 2 * tg;
#pragma unroll
                for (int q = 0; q < 4; q++) {
                    int lr = r0 + ((q >= 2) ? 8 : 0);
                    int cc = c0 + (q & 1);
                    float val = ga[nf][q] + g_d[chunk * 64 + cc];
                    if (chunk < 4)
                        g_Gh[((size_t)b * 4096 + chunk * 1024 + m0 + lr) * 64 + cc] =
                            __float2half_rn(val);
                    else
                        g_u[((size_t)b * NN + m0 + lr) * 64 + cc] = val;
                }
            }
        }
    }
}

// ---------------- kernel 4: final readout ----------------
__global__ __launch_bounds__(256) void final_kernel(const float* __restrict__ ann,
                                                    const float* __restrict__ Wh,
                                                    const float* __restrict__ bh,
                                                    const float* __restrict__ Wo,
                                                    const float* __restrict__ bo,
                                                    float* __restrict__ out) {
    __shared__ float Whs[72 * 64];
    __shared__ float rowbuf[4][72];
    __shared__ float red[4][2];
    int tid = threadIdx.x;
    for (int i = tid; i < 72 * 64; i += 256) Whs[i] = Wh[i];
    int sub = tid >> 6, j = tid & 63;
    int rglob = blockIdx.x * 4 + sub;
    rowbuf[sub][j] = g_h[(size_t)rglob * 64 + j];
    if (j < 8) rowbuf[sub][64 + j] = ann[(size_t)rglob * 8 + j];
    __syncthreads();

    float acc = bh[j];
#pragma unroll
    for (int k = 0; k < 72; k++) acc += rowbuf[sub][k] * Whs[k * 64 + j];
    float o = tanhf(acc) * Wo[j];
#pragma unroll
    for (int off = 16; off; off >>= 1) o += __shfl_down_sync(0xffffffffu, o, off);
    if ((tid & 31) == 0) red[sub][j >> 5] = o;
    __syncthreads();
    if (j == 0) out[rglob] = red[sub][0] + red[sub][1] + bo[0];
}

// ---------------- host ----------------
extern "C" void kernel_launch(void* const* d_in, const int* in_sizes, int n_in,
                              void* d_out, int out_size) {
    (void)in_sizes; (void)n_in; (void)out_size;
    const float* init = (const float*)d_in[0];
    const float* ann  = (const float*)d_in[1];
    const float* adj  = (const float*)d_in[2];
    const float* We   = (const float*)d_in[3];
    const float* be   = (const float*)d_in[4];
    const float* Wg   = (const float*)d_in[5];
    const float* bg   = (const float*)d_in[6];
    const float* Wh   = (const float*)d_in[7];
    const float* bh   = (const float*)d_in[8];
    const float* Wo   = (const float*)d_in[9];
    const float* bo   = (const float*)d_in[10];
    float* out = (float*)d_out;

    cudaFuncSetAttribute(gemm_kernel, cudaFuncAttributeMaxDynamicSharedMemorySize, GEMM_SMEM);
    cudaFuncSetAttribute(update_kernel, cudaFuncAttributeMaxDynamicSharedMemorySize, UPD_SMEM);
    cudaFuncSetAttribute(gbuild_kernel, cudaFuncAttributeMaxDynamicSharedMemorySize, GB_SMEM);

    cudaMemcpyToSymbolAsync(g_h, init, (size_t)BB * NN * 64 * sizeof(float), 0,
                            cudaMemcpyDeviceToDevice, 0);
    conv_kernel<<<16384, 256>>>((const float4*)adj);
    build_C_kernel<<<80, 256>>>(We, be, Wg);
    gbuild_kernel<<<dim3(16, BB), 128, GB_SMEM>>>();
    for (int s = 0; s < NSTEPS; s++) {
        gemm_kernel<<<dim3(16, BB, KSPLIT), 128, GEMM_SMEM>>>();
        update_kernel<<<dim3(16, BB), 256, UPD_SMEM>>>(bg, (s < NSTEPS - 1) ? 1 : 0);
    }
    final_kernel<<<2048, 256>>>(ann, Wh, bh, Wo, bo, out);
}